// round 1
// baseline (speedup 1.0000x reference)
#include <cuda_runtime.h>

#define BB   16
#define HH   512
#define WW   512
#define HW   (HH * WW)
#define NPIX (BB * HW)

// Persistent scratch (allocation-free rule: __device__ globals).
// g_kernel: 9 planes of [B*H*W] softmaxed weights, plane-major so the
// message pass reads each plane fully coalesced (float4).
__device__ float g_kernel[9][NPIX];   // 151 MB
__device__ float g_buf[2][NPIX];      // ping-pong pred buffers, 32 MB

// ---------------------------------------------------------------------------
// Pass 1: per-pixel 3x3 Gaussian kernel + softmax over the 9 entries.
// entry_k = valid ? exp(-0.5*(t0*dx^2 + t1*dy^2 + t2*(255*dI)^2)) : 0
// kernel  = softmax(entry)   (zeros DO contribute exp(0)=1, per reference)
// ---------------------------------------------------------------------------
__global__ __launch_bounds__(256)
void build_kernel(const float* __restrict__ image,
                  const float* __restrict__ theta)
{
    int idx = blockIdx.x * 256 + threadIdx.x;
    if (idx >= NPIX) return;
    int w = idx & (WW - 1);
    int h = (idx >> 9) & (HH - 1);
    int b = idx >> 18;

    float t0 = theta[0], t1 = theta[1], t2 = theta[2];
    const float* img = image + b * HW;
    float c = img[h * WW + w] * 255.0f;

    float e[9];
#pragma unroll
    for (int k = 0; k < 9; k++) {
        int dx = k / 3 - 1;           // row offset
        int dy = k % 3 - 1;           // col offset
        int hh = h + dx, ww = w + dy;
        float v = 0.0f;
        if ((unsigned)hh < HH && (unsigned)ww < WW) {
            float d    = img[hh * WW + ww] * 255.0f - c;
            float dist = t0 * (float)(dx * dx) + t1 * (float)(dy * dy) + t2 * d * d;
            v = __expf(-0.5f * dist);
        }
        e[k] = v;
    }

    // softmax over the 9 entries (values in [0,1], no overflow concern)
    float s = 0.0f;
#pragma unroll
    for (int k = 0; k < 9; k++) { e[k] = __expf(e[k]); s += e[k]; }
    float inv = 1.0f / s;
#pragma unroll
    for (int k = 0; k < 9; k++) g_kernel[k][idx] = e[k] * inv;
}

// ---------------------------------------------------------------------------
// Pass 2 (x10): pred_out = 0.5*unary + 0.5*weight * sum_k kernel_k * pred[nbr_k]
// Each thread handles 4 consecutive pixels along W (float4 on kernel planes,
// unary, and output; pred neighborhood read as float4 + 2 edge scalars/row).
// ---------------------------------------------------------------------------
__global__ __launch_bounds__(256)
void message_pass(const float* __restrict__ pin,
                  const float* __restrict__ unary,
                  const float* __restrict__ weight,
                  float* __restrict__ pout)
{
    int q = blockIdx.x * 256 + threadIdx.x;          // quad index
    if (q >= NPIX / 4) return;
    int w4 = (q & (WW / 4 - 1)) << 2;                // starting col of this quad
    int h  = (q >> 7) & (HH - 1);
    int b  = q >> 16;
    int base    = b * HW;
    int rowbase = base + h * WW;

    // pred neighborhood: 3 rows x cols [w4-1 .. w4+4], zero-padded
    float row[3][6];
#pragma unroll
    for (int r = 0; r < 3; r++) {
        int hh = h + r - 1;
        if ((unsigned)hh >= HH) {
#pragma unroll
            for (int c = 0; c < 6; c++) row[r][c] = 0.0f;
        } else {
            const float* p = pin + base + hh * WW;
            float4 v = *(const float4*)(p + w4);
            row[r][1] = v.x; row[r][2] = v.y; row[r][3] = v.z; row[r][4] = v.w;
            row[r][0] = (w4 > 0)      ? p[w4 - 1] : 0.0f;
            row[r][5] = (w4 + 4 < WW) ? p[w4 + 4] : 0.0f;
        }
    }

    float a0 = 0.f, a1 = 0.f, a2 = 0.f, a3 = 0.f;
#pragma unroll
    for (int k = 0; k < 9; k++) {
        int dx = k / 3;   // 0..2  -> row index
        int dy = k % 3;   // 0..2  -> col shift
        float4 kk = *(const float4*)&g_kernel[k][rowbase + w4];
        a0 += kk.x * row[dx][dy + 0];
        a1 += kk.y * row[dx][dy + 1];
        a2 += kk.z * row[dx][dy + 2];
        a3 += kk.w * row[dx][dy + 3];
    }

    float hw = 0.5f * weight[0];
    float4 u = *(const float4*)(unary + rowbase + w4);
    float4 o;
    o.x = 0.5f * u.x + hw * a0;
    o.y = 0.5f * u.y + hw * a1;
    o.z = 0.5f * u.z + hw * a2;
    o.w = 0.5f * u.w + hw * a3;
    *(float4*)(pout + rowbase + w4) = o;
}

extern "C" void kernel_launch(void* const* d_in, const int* in_sizes, int n_in,
                              void* d_out, int out_size)
{
    const float* image  = (const float*)d_in[0];
    const float* unary  = (const float*)d_in[1];
    const float* theta  = (const float*)d_in[2];
    const float* weight = (const float*)d_in[3];
    float* out = (float*)d_out;

    void* baddr = nullptr;
    cudaGetSymbolAddress(&baddr, g_buf);   // non-stream API: capture-safe
    float* buf0 = (float*)baddr;
    float* buf1 = buf0 + NPIX;

    build_kernel<<<NPIX / 256, 256>>>(image, theta);

    for (int i = 0; i < 10; i++) {
        const float* pin  = (i == 0) ? unary : (((i - 1) & 1) ? buf1 : buf0);
        float*       pout = (i == 9) ? out   : ((i & 1) ? buf1 : buf0);
        message_pass<<<(NPIX / 4) / 256, 256>>>(pin, unary, weight, pout);
    }
}

// round 2
// speedup vs baseline: 1.4979x; 1.4979x over previous
#include <cuda_runtime.h>
#include <cuda_fp16.h>

#define BB   16
#define HH   512
#define WW   512
#define HW   (HH * WW)
#define NPIX (BB * HW)

// Persistent scratch (allocation-free rule: __device__ globals).
// g_kernel: 9 planes of [B*H*W] softmaxed weights in fp16 (75 MB) so the
// whole per-pass working set (~123 MB) fits in L2.
__device__ __half g_kernel[9][NPIX];  // 75 MB
__device__ float  g_buf[2][NPIX];     // ping-pong pred buffers, 32 MB

// ---------------------------------------------------------------------------
// Pass 1: per-pixel 3x3 Gaussian kernel + softmax over the 9 entries.
// entry_k = valid ? exp(-0.5*(t0*dx^2 + t1*dy^2 + t2*(255*dI)^2)) : 0
// kernel  = softmax(entry)   (zeros DO contribute exp(0)=1, per reference)
// ---------------------------------------------------------------------------
__global__ __launch_bounds__(256)
void build_kernel(const float* __restrict__ image,
                  const float* __restrict__ theta)
{
    int idx = blockIdx.x * 256 + threadIdx.x;
    if (idx >= NPIX) return;
    int w = idx & (WW - 1);
    int h = (idx >> 9) & (HH - 1);
    int b = idx >> 18;

    float t0 = theta[0], t1 = theta[1], t2 = theta[2];
    const float* img = image + b * HW;
    float c = img[h * WW + w] * 255.0f;

    float e[9];
#pragma unroll
    for (int k = 0; k < 9; k++) {
        int dx = k / 3 - 1;           // row offset
        int dy = k % 3 - 1;           // col offset
        int hh = h + dx, ww = w + dy;
        float v = 0.0f;
        if ((unsigned)hh < HH && (unsigned)ww < WW) {
            float d    = img[hh * WW + ww] * 255.0f - c;
            float dist = t0 * (float)(dx * dx) + t1 * (float)(dy * dy) + t2 * d * d;
            v = __expf(-0.5f * dist);
        }
        e[k] = v;
    }

    // softmax over the 9 entries (values in [0,1], no overflow concern)
    float s = 0.0f;
#pragma unroll
    for (int k = 0; k < 9; k++) { e[k] = __expf(e[k]); s += e[k]; }
    float inv = 1.0f / s;
#pragma unroll
    for (int k = 0; k < 9; k++) g_kernel[k][idx] = __float2half(e[k] * inv);
}

// ---------------------------------------------------------------------------
// Pass 2 (x10): pred_out = 0.5*unary + 0.5*weight * sum_k kernel_k * pred[nbr_k]
// Each thread handles 4 consecutive pixels along W. Kernel planes are fp16,
// read as one 8-byte load per plane per quad; accumulation in fp32.
// ---------------------------------------------------------------------------
__global__ __launch_bounds__(256)
void message_pass(const float* __restrict__ pin,
                  const float* __restrict__ unary,
                  const float* __restrict__ weight,
                  float* __restrict__ pout)
{
    int q = blockIdx.x * 256 + threadIdx.x;          // quad index
    if (q >= NPIX / 4) return;
    int w4 = (q & (WW / 4 - 1)) << 2;                // starting col of this quad
    int h  = (q >> 7) & (HH - 1);
    int b  = q >> 16;
    int base    = b * HW;
    int rowbase = base + h * WW;

    // pred neighborhood: 3 rows x cols [w4-1 .. w4+4], zero-padded
    float row[3][6];
#pragma unroll
    for (int r = 0; r < 3; r++) {
        int hh = h + r - 1;
        if ((unsigned)hh >= HH) {
#pragma unroll
            for (int c = 0; c < 6; c++) row[r][c] = 0.0f;
        } else {
            const float* p = pin + base + hh * WW;
            float4 v = *(const float4*)(p + w4);
            row[r][1] = v.x; row[r][2] = v.y; row[r][3] = v.z; row[r][4] = v.w;
            row[r][0] = (w4 > 0)      ? p[w4 - 1] : 0.0f;
            row[r][5] = (w4 + 4 < WW) ? p[w4 + 4] : 0.0f;
        }
    }

    float a0 = 0.f, a1 = 0.f, a2 = 0.f, a3 = 0.f;
#pragma unroll
    for (int k = 0; k < 9; k++) {
        int dx = k / 3;   // 0..2  -> row index
        int dy = k % 3;   // 0..2  -> col shift
        // 4 fp16 weights = 8 bytes
        uint2 raw = *(const uint2*)&g_kernel[k][rowbase + w4];
        float2 k01 = __half22float2(*reinterpret_cast<const __half2*>(&raw.x));
        float2 k23 = __half22float2(*reinterpret_cast<const __half2*>(&raw.y));
        a0 += k01.x * row[dx][dy + 0];
        a1 += k01.y * row[dx][dy + 1];
        a2 += k23.x * row[dx][dy + 2];
        a3 += k23.y * row[dx][dy + 3];
    }

    float hw = 0.5f * weight[0];
    float4 u = *(const float4*)(unary + rowbase + w4);
    float4 o;
    o.x = 0.5f * u.x + hw * a0;
    o.y = 0.5f * u.y + hw * a1;
    o.z = 0.5f * u.z + hw * a2;
    o.w = 0.5f * u.w + hw * a3;
    *(float4*)(pout + rowbase + w4) = o;
}

extern "C" void kernel_launch(void* const* d_in, const int* in_sizes, int n_in,
                              void* d_out, int out_size)
{
    const float* image  = (const float*)d_in[0];
    const float* unary  = (const float*)d_in[1];
    const float* theta  = (const float*)d_in[2];
    const float* weight = (const float*)d_in[3];
    float* out = (float*)d_out;

    void* baddr = nullptr;
    cudaGetSymbolAddress(&baddr, g_buf);   // non-stream API: capture-safe
    float* buf0 = (float*)baddr;
    float* buf1 = buf0 + NPIX;

    build_kernel<<<NPIX / 256, 256>>>(image, theta);

    for (int i = 0; i < 10; i++) {
        const float* pin  = (i == 0) ? unary : (((i - 1) & 1) ? buf1 : buf0);
        float*       pout = (i == 9) ? out   : ((i & 1) ? buf1 : buf0);
        message_pass<<<(NPIX / 4) / 256, 256>>>(pin, unary, weight, pout);
    }
}

// round 4
// speedup vs baseline: 1.9875x; 1.3268x over previous
#include <cuda_runtime.h>
#include <cuda_fp16.h>
#include <cstdint>

#define BB   16
#define HH   512
#define WW   512
#define HW   (HH * WW)
#define NPIX (BB * HW)

typedef unsigned int u32;

// Symmetric factorization: A_d(p) = A_{-d}(p+d) for the unnormalized entries,
// center entry is the constant exp(1). Store 4 forward-direction planes of
// A = exp(e) (fp16) + one plane of invS' = 0.5*weight/S (fp16).
// Dirs: 0=(0,1) 1=(1,-1) 2=(1,0) 3=(1,1)
__device__ __half g_A[4][NPIX];    // 33.6 MB
__device__ __half g_invS[NPIX];    //  8.4 MB
__device__ float  g_buf[2][NPIX];  // ping-pong pred buffers

#define AC 2.7182818284590452f     // exp(1): center softmax-numerator

__global__ __launch_bounds__(256)
void build_kernel(const float* __restrict__ image,
                  const float* __restrict__ theta,
                  const float* __restrict__ weight)
{
    int idx = blockIdx.x * 256 + threadIdx.x;
    if (idx >= NPIX) return;
    int w = idx & (WW - 1);
    int h = (idx >> 9) & (HH - 1);
    int b = idx >> 18;

    float t0 = theta[0], t1 = theta[1], t2 = theta[2];
    const float* img = image + b * HW;
    float c = img[h * WW + w] * 255.0f;

    float A[9];
#pragma unroll
    for (int k = 0; k < 9; k++) {
        int dx = k / 3 - 1, dy = k % 3 - 1;
        int hh = h + dx, ww = w + dy;
        float e = 0.0f;
        if ((unsigned)hh < HH && (unsigned)ww < WW) {
            float d    = img[hh * WW + ww] * 255.0f - c;
            float dist = t0 * (float)(dx * dx) + t1 * (float)(dy * dy) + t2 * d * d;
            e = __expf(-0.5f * dist);
        }
        A[k] = __expf(e);          // invalid neighbor -> exp(0) = 1
    }

    // Sum S from the fp16-ROUNDED values: exactly what the message pass will
    // read (forward at p and backward at p-d are bit-identical by symmetry).
    float S = AC;
#pragma unroll
    for (int k = 0; k < 9; k++)
        if (k != 4) S += __half2float(__float2half(A[k]));

    float invSw = 0.5f * weight[0] / S;
    g_A[0][idx] = __float2half(A[5]);   // (0, 1)
    g_A[1][idx] = __float2half(A[6]);   // (1,-1)
    g_A[2][idx] = __float2half(A[7]);   // (1, 0)
    g_A[3][idx] = __float2half(A[8]);   // (1, 1)
    g_invS[idx] = __float2half(invSw);
}

__device__ __forceinline__ float2 h2f(const u32 u) {
    return __half22float2(*reinterpret_cast<const __half2*>(&u));
}

__global__ __launch_bounds__(256)
void message_pass(const float* __restrict__ pin,
                  const float* __restrict__ unary,
                  float* __restrict__ pout)
{
    int q = blockIdx.x * 256 + threadIdx.x;          // quad index
    if (q >= NPIX / 4) return;
    int w4 = (q & (WW / 4 - 1)) << 2;
    int h  = (q >> 7) & (HH - 1);
    int b  = q >> 16;
    int base    = b * HW;
    int rowbase = base + h * WW;

    // pred neighborhood: 3 rows x cols [w4-1 .. w4+4], zero-padded
    float row[3][6];
#pragma unroll
    for (int r = 0; r < 3; r++) {
        int hh = h + r - 1;
        if ((unsigned)hh >= HH) {
#pragma unroll
            for (int c = 0; c < 6; c++) row[r][c] = 0.0f;
        } else {
            const float* p = pin + base + hh * WW;
            float4 v = *(const float4*)(p + w4);
            row[r][1] = v.x; row[r][2] = v.y; row[r][3] = v.z; row[r][4] = v.w;
            row[r][0] = (w4 > 0)      ? p[w4 - 1] : 0.0f;
            row[r][5] = (w4 + 4 < WW) ? p[w4 + 4] : 0.0f;
        }
    }

    // center term
    float a0 = AC * row[1][1], a1 = AC * row[1][2];
    float a2 = AC * row[1][3], a3 = AC * row[1][4];

    const u32 ONES2 = 0x3C003C00u;  // half2(1,1)
    const __half* P0 = g_A[0], *P1 = g_A[1], *P2 = g_A[2], *P3 = g_A[3];
    int up = rowbase - WW + w4;          // row h-1 base index (valid iff h>0)
    int cw = rowbase + w4;

    // ---- dir0 (0,1): forward halves cover cols w4..w4+3 (also reused by B0)
    {
        uint2 rv = *(const uint2*)&P0[cw];
        float2 f01 = h2f(rv.x), f23 = h2f(rv.y);
        a0 += f01.x * row[1][2]; a1 += f01.y * row[1][3];
        a2 += f23.x * row[1][4]; a3 += f23.y * row[1][5];
        // backward (0,-1): plane0 at (h, w4-1..w4+2), OOB col -> 1
        u32 ta = (w4 > 0) ? *(const u32*)&P0[cw - 2] : ONES2;
        float2 fa = h2f(ta);
        a0 += fa.y  * row[1][0]; a1 += f01.x * row[1][1];
        a2 += f01.y * row[1][2]; a3 += f23.x * row[1][3];
    }
    // ---- dir1 (1,-1): forward
    {
        uint2 rv = *(const uint2*)&P1[cw];
        float2 f01 = h2f(rv.x), f23 = h2f(rv.y);
        a0 += f01.x * row[2][0]; a1 += f01.y * row[2][1];
        a2 += f23.x * row[2][2]; a3 += f23.y * row[2][3];
        // backward (-1,1): plane1 at (h-1, w4+1..w4+4), OOB -> 1
        u32 tb = ONES2, tc = ONES2, td = ONES2;
        if (h > 0) {
            tb = *(const u32*)&P1[up];
            tc = *(const u32*)&P1[up + 2];
            if (w4 + 4 < WW) td = *(const u32*)&P1[up + 4];
        }
        float2 fb = h2f(tb), fc = h2f(tc), fd = h2f(td);
        a0 += fb.y * row[0][2]; a1 += fc.x * row[0][3];
        a2 += fc.y * row[0][4]; a3 += fd.x * row[0][5];
    }
    // ---- dir2 (1,0): forward
    {
        uint2 rv = *(const uint2*)&P2[cw];
        float2 f01 = h2f(rv.x), f23 = h2f(rv.y);
        a0 += f01.x * row[2][1]; a1 += f01.y * row[2][2];
        a2 += f23.x * row[2][3]; a3 += f23.y * row[2][4];
        // backward (-1,0): plane2 at (h-1, w4..w4+3) aligned, OOB row -> 1
        uint2 bv; bv.x = ONES2; bv.y = ONES2;
        if (h > 0) bv = *(const uint2*)&P2[up];
        float2 b01 = h2f(bv.x), b23 = h2f(bv.y);
        a0 += b01.x * row[0][1]; a1 += b01.y * row[0][2];
        a2 += b23.x * row[0][3]; a3 += b23.y * row[0][4];
    }
    // ---- dir3 (1,1): forward
    {
        uint2 rv = *(const uint2*)&P3[cw];
        float2 f01 = h2f(rv.x), f23 = h2f(rv.y);
        a0 += f01.x * row[2][2]; a1 += f01.y * row[2][3];
        a2 += f23.x * row[2][4]; a3 += f23.y * row[2][5];
        // backward (-1,-1): plane3 at (h-1, w4-1..w4+2), OOB -> 1
        u32 ta = ONES2, tb = ONES2, tc = ONES2;
        if (h > 0) {
            if (w4 > 0) ta = *(const u32*)&P3[up - 2];
            tb = *(const u32*)&P3[up];
            tc = *(const u32*)&P3[up + 2];
        }
        float2 fa = h2f(ta), fb = h2f(tb), fc = h2f(tc);
        a0 += fa.y * row[0][0]; a1 += fb.x * row[0][1];
        a2 += fb.y * row[0][2]; a3 += fc.x * row[0][3];
    }

    // normalize (0.5*weight folded in) + unary
    uint2 sv = *(const uint2*)&g_invS[cw];
    float2 s01 = h2f(sv.x), s23 = h2f(sv.y);
    float4 u = *(const float4*)(unary + rowbase + w4);
    float4 o;
    o.x = 0.5f * u.x + s01.x * a0;
    o.y = 0.5f * u.y + s01.y * a1;
    o.z = 0.5f * u.z + s23.x * a2;
    o.w = 0.5f * u.w + s23.y * a3;
    *(float4*)(pout + rowbase + w4) = o;
}

extern "C" void kernel_launch(void* const* d_in, const int* in_sizes, int n_in,
                              void* d_out, int out_size)
{
    const float* image  = (const float*)d_in[0];
    const float* unary  = (const float*)d_in[1];
    const float* theta  = (const float*)d_in[2];
    const float* weight = (const float*)d_in[3];
    float* out = (float*)d_out;

    void* baddr = nullptr;
    cudaGetSymbolAddress(&baddr, g_buf);   // non-stream API: capture-safe
    float* buf0 = (float*)baddr;
    float* buf1 = buf0 + NPIX;

    build_kernel<<<NPIX / 256, 256>>>(image, theta, weight);

    for (int i = 0; i < 10; i++) {
        const float* pin  = (i == 0) ? unary : (((i - 1) & 1) ? buf1 : buf0);
        float*       pout = (i == 9) ? out   : ((i & 1) ? buf1 : buf0);
        message_pass<<<(NPIX / 4) / 256, 256>>>(pin, unary, pout);
    }
}